// round 14
// baseline (speedup 1.0000x reference)
#include <cuda_runtime.h>
#include <math.h>

#define NBB   32
#define NAA   5
#define NCC   80
#define NHH   64
#define NWW   64
#define MAXTG 50
#define CHN   (5 + NCC)          // 85
#define PLANE (NHH * NWW)        // 4096
#define GRID_MAIN (NBB * NAA * 4) // 640
#define TPB   512                 // 2 cells per thread
#define L2E   1.44269504088896f
#define LN2   0.69314718055995f

// -------- device scratch --------
__device__ float4   g_A[NBB * MAXTG];   // {gl, gr, gt, gb}
__device__ float4   g_B[NBB * MAXTG];   // {-0.375*gw*gh, cellg(int bits), tiou, cls}
__device__ float4   g_C[NBB * MAXTG];   // {tx, ty, tw, th}
__device__ int2     g_D[NBB * MAXTG];   // {class-ch0 gmem offset or -1, class idx}
__device__ double   g_loss;
__device__ unsigned g_count;

__constant__ float c_anch[10] = {
    42.3f / 32.f, 55.4f / 32.f, 102.2f / 32.f, 128.3f / 32.f, 161.8f / 32.f,
    259.2f / 32.f, 303.1f / 32.f, 154.9f / 32.f, 359.6f / 32.f, 320.2f / 32.f
};

__device__ __forceinline__ float sigf(float v) {
    return 1.0f / (1.0f + exp2f(v * -L2E));
}

// -------- kernel 1: per-target precompute (32 blocks x 64 threads) --------
__global__ void __launch_bounds__(64) k_targets(const float* __restrict__ out,
                                                const float* __restrict__ tgt) {
    __shared__ int      s_cellg[MAXTG];
    __shared__ unsigned zmask[2];

    int b = blockIdx.x;
    int t = threadIdx.x;

    if (b == 0 && t == 0) { g_loss = 0.0; g_count = 0u; }

    float cls = 0.f, fx = 0.f, fy = 0.f, fw = 0.f, fh = 0.f;
    bool nzf = true;
    if (t < MAXTG) {
        const float* p = tgt + (b * MAXTG + t) * 5;
        cls = p[0]; fx = p[1]; fy = p[2]; fw = p[3]; fh = p[4];
        nzf = (fx != 0.0f);
    }

    unsigned zeros = __ballot_sync(0xffffffffu, !nzf);
    if ((t & 31) == 0) zmask[t >> 5] = zeros;
    __syncthreads();
    int fz0 = __ffs((int)zmask[0]);
    int fz1 = __ffs((int)zmask[1]);
    int first_zero = fz0 ? (fz0 - 1) : (fz1 ? 32 + fz1 - 1 : 1000);

    bool valid = (t < MAXTG) && (t < first_zero);
    int cellg = -1;
    int clsoff = -1;
    int idx = b * MAXTG + t;

    if (t < MAXTG) {
        float gx = fx * (float)NWW;
        float gy = fy * (float)NHH;
        float gw = fw * (float)NWW;
        float gh = fh * (float)NHH;

        int best = 0;
        float bestv = -1e30f;
#pragma unroll
        for (int an = 0; an < NAA; an++) {
            float aw = c_anch[2 * an], ah = c_anch[2 * an + 1];
            float inter = fminf(gw, aw) * fminf(gh, ah);
            float uni = gw * gh + aw * ah - inter;
            float v = inter / uni;
            if (v > bestv) { bestv = v; best = an; }
        }

        int gi = min(max((int)gx, 0), NWW - 1);
        int gj = min(max((int)gy, 0), NHH - 1);
        float awb = c_anch[2 * best], ahb = c_anch[2 * best + 1];

        const float* ob = out + (size_t)(b * (NAA * CHN) + best * CHN) * PLANE
                              + gj * NWW + gi;
        float xx = sigf(ob[0]);
        float yy = sigf(ob[PLANE]);
        float ww = ob[2 * PLANE];
        float hh = ob[3 * PLANE];
        float px = xx + (float)gi;
        float py = yy + (float)gj;
        float pw = exp2f(ww * L2E) * awb;
        float ph = exp2f(hh * L2E) * ahb;

        float iw = fminf(gx + 0.5f * gw, px + 0.5f * pw)
                 - fmaxf(gx - 0.5f * gw, px - 0.5f * pw);
        float ih = fminf(gy + 0.5f * gh, py + 0.5f * ph)
                 - fmaxf(gy - 0.5f * gh, py - 0.5f * ph);
        float inter = fmaxf(iw, 0.f) * fmaxf(ih, 0.f);
        float uni = gw * gh + pw * ph - inter;
        float tiou = inter / uni;

        g_C[idx] = make_float4(gx - (float)gi, gy - (float)gj,
                               log2f(gw / awb) * LN2, log2f(gh / ahb) * LN2);

        cellg = valid ? (best * PLANE + gj * NWW + gi) : -1;
        clsoff = ((b * NAA + best) * CHN + 5) * PLANE + gj * NWW + gi;
        if (valid) {
            g_A[idx] = make_float4(gx - 0.5f * gw, gx + 0.5f * gw,
                                   gy - 0.5f * gh, gy + 0.5f * gh);
            g_B[idx] = make_float4(-0.375f * gw * gh, __int_as_float(cellg), tiou, cls);
        } else {
            g_A[idx] = make_float4(1e30f, -1e30f, 1e30f, -1e30f);
            g_B[idx] = make_float4(0.f, __int_as_float(-1), tiou, cls);
        }
        s_cellg[t] = cellg;
    }
    __syncthreads();

    if (t < MAXTG) {
        // winner = last-t-wins per cell (JAX flat scatter semantics)
        bool winner = valid;
        for (int u = t + 1; u < MAXTG; u++)
            winner = winner && (s_cellg[u] != cellg);
        g_D[idx] = make_int2(winner ? clsoff : -1, (int)cls);
    }
}

// -------- kernel 2: per-cell loss + distributed class loss + final write ----
// grid = 640 blocks; block = 512 threads; thread = 2 consecutive cells.
// Warps 13..15 additionally own up to one class-loss job each.
__global__ void __launch_bounds__(TPB, 2) k_main(const float* __restrict__ out,
                                                 float* __restrict__ outp) {
    __shared__ float2 s_X[MAXTG];       // {gl, gr}
    __shared__ float2 s_Y[MAXTG];       // {gt, gb}
    __shared__ float4 s_Ct[MAXTG];      // {tx, ty, tw, th}
    __shared__ float  s_nga[MAXTG];     // -0.375*gw*gh
    __shared__ float  s_ti[MAXTG];      // tiou
    __shared__ int    s_map[1024];      // winning target per local cell (-1 none)

    int blk = blockIdx.x;
    int q = blk & 3;
    int a = (blk >> 2) % NAA;
    int b = blk / (NAA * 4);
    int tid = threadIdx.x;
    int wid = tid >> 5;
    int lane = tid & 31;

    s_map[tid * 2]     = -1;
    s_map[tid * 2 + 1] = -1;

    int blockbase = a * PLANE + q * 1024;

    if (tid < MAXTG) {
        int o = b * MAXTG + tid;
        float4 bx = g_A[o];
        s_X[tid] = make_float2(bx.x, bx.y);
        s_Y[tid] = make_float2(bx.z, bx.w);
        s_Ct[tid] = g_C[o];
        float4 mb = g_B[o];
        s_nga[tid] = mb.x;
        s_ti[tid]  = mb.z;
    }
    __syncthreads();

    // scatter: max-t wins == JAX last-write-wins
    if (tid < MAXTG) {
        int cellg = __float_as_int(g_B[b * MAXTG + tid].y);
        unsigned m = (unsigned)(cellg - blockbase);
        if (m < 1024u) atomicMax(&s_map[m], tid);
    }

    // ---- class-loss job: issue gathers EARLY so DRAM latency overlaps ----
    bool have_cls = false;
    float cv1 = -1e30f, cv2 = -1e30f, cv3 = -1e30f, cpick = 0.f;
    if (wid >= 13) {
        int tt = (a * 4 + q) + 20 * (wid - 13);
        if (tt < MAXTG) {
            int2 d = g_D[b * MAXTG + tt];
            if (d.x >= 0) {
                have_cls = true;
                const float* cp = out + d.x;
                cv1 = cp[lane * PLANE];
                cv2 = cp[(lane + 32) * PLANE];
                if (lane < 16) cv3 = cp[(lane + 64) * PLANE];
                cpick = cp[d.y * PLANE];
            }
        }
    }

    int lin = q * 1024 + tid * 2;
    int j = lin >> 6;
    int i0 = lin & 63;

    const float* base = out + (size_t)(b * (NAA * CHN) + a * CHN) * PLANE + lin;
    float2 v0 = *reinterpret_cast<const float2*>(base);
    float2 v1 = *reinterpret_cast<const float2*>(base + PLANE);
    float2 v2 = *reinterpret_cast<const float2*>(base + 2 * PLANE);
    float2 v3 = *reinterpret_cast<const float2*>(base + 3 * PLANE);

    float o0[2] = {v0.x, v0.y};
    float o1[2] = {v1.x, v1.y};
    float o2[2] = {v2.x, v2.y};
    float o3[2] = {v3.x, v3.y};

    float aw = c_anch[2 * a], ah = c_anch[2 * a + 1];

    float PXL[2], PXR[2], PYT[2], PYB[2], nPA[2], F[2];
#pragma unroll
    for (int k = 0; k < 2; k++) {
        float pw = exp2f(o2[k] * L2E) * aw;
        float ph = exp2f(o3[k] * L2E) * ah;
        float px = sigf(o0[k]) + (float)(i0 + k);
        float py = sigf(o1[k]) + (float)j;
        PXL[k] = px - 0.5f * pw;
        PXR[k] = px + 0.5f * pw;
        PYT[k] = py - 0.5f * ph;
        PYB[k] = py + 0.5f * ph;
        nPA[k] = -0.375f * pw * ph;
        F[k] = -1e30f;
    }

    // warp-wide y-band (each warp = one grid row); used for uniform culling
    float wT = fminf(PYT[0], PYT[1]);
    float wB = fmaxf(PYB[0], PYB[1]);
#pragma unroll
    for (int o = 16; o > 0; o >>= 1) {
        wT = fminf(wT, __shfl_xor_sync(0xffffffffu, wT, o));
        wB = fmaxf(wB, __shfl_xor_sync(0xffffffffu, wB, o));
    }

    __syncthreads();

    // SIL loop with warp-uniform y-cull.
    // IoU>0.6  <=>  max(iw,0)*ih - 0.375*(pa+ga) > 0; skip t if the target's
    // y-interval misses the warp's y-band (then ih<0 for all lanes => pm<0).
    for (int t = 0; t < MAXTG; t++) {
        float2 gy = s_Y[t];                  // {gt, gb}
        if (gy.x > wB || gy.y < wT) continue;   // warp-uniform skip
        float2 gx = s_X[t];                  // {gl, gr}
        float nga = s_nga[t];
#pragma unroll
        for (int k = 0; k < 2; k++) {
            float iw  = fminf(PXR[k], gx.y) - fmaxf(PXL[k], gx.x);
            float iwc = fmaxf(iw, 0.f);
            float ih  = fminf(PYB[k], gy.y) - fmaxf(PYT[k], gy.x);
            float pm  = iwc * ih + (nPA[k] + nga);
            F[k] = fmaxf(F[k], pm);
        }
    }

    // ---- per-cell epilogue ----
    float2 v4 = *reinterpret_cast<const float2*>(base + 4 * PLANE);
    float e4[2] = {v4.x, v4.y};

    double acc = 0.0;
#pragma unroll
    for (int k = 0; k < 2; k++) {
        float X = sigf(o0[k]);
        float Y = sigf(o1[k]);
        float W = o2[k];
        float H = o3[k];
        float C = sigf(e4[k]);
        int S = s_map[tid * 2 + k];
        if (S < 0) {
            float dx = X - 0.5f;
            float dy = Y - 0.5f;
            float l = dx * dx + dy * dy + W * W + H * H;
            float lc = (F[k] > 0.f) ? 0.f : C * C;
            acc += 0.5 * (double)(l + lc);
        } else {
            float4 tc = s_Ct[S];
            float dx = X - tc.x;
            float dy = Y - tc.y;
            float dw = W - tc.z;
            float dh = H - tc.w;
            float dc = C - s_ti[S];
            float l = dx * dx + dy * dy + dw * dw + dh * dh;
            acc += 0.5 * (double)l + 2.5 * (double)(dc * dc);
        }
    }

    // ---- class-loss epilogue (warps 13..15, data already in flight) ----
    if (have_cls) {
        float m = fmaxf(fmaxf(cv1, cv2), cv3);
#pragma unroll
        for (int o = 16; o > 0; o >>= 1)
            m = fmaxf(m, __shfl_xor_sync(0xffffffffu, m, o));
        float e = exp2f((cv1 - m) * L2E) + exp2f((cv2 - m) * L2E)
                + ((lane < 16) ? exp2f((cv3 - m) * L2E) : 0.f);
#pragma unroll
        for (int o = 16; o > 0; o >>= 1)
            e += __shfl_xor_sync(0xffffffffu, e, o);
        if (lane == 0) {
            float lz = m + log2f(e) * LN2;
            acc += (double)(lz - cpick);
        }
    }

    // ---- block reduction (16 warps) ----
    for (int off = 16; off > 0; off >>= 1)
        acc += __shfl_down_sync(0xffffffffu, acc, off);
    __shared__ double s_red[16];
    if ((tid & 31) == 0) s_red[tid >> 5] = acc;
    __syncthreads();
    if (tid == 0) {
        double s = 0.0;
        for (int wsl = 0; wsl < 16; wsl++) s += s_red[wsl];
        atomicAdd(&g_loss, s);
        __threadfence();
        unsigned old = atomicAdd(&g_count, 1u);
        if (old == (unsigned)(GRID_MAIN - 1)) {
            double total = *(volatile double*)&g_loss;
            outp[0] = (float)total;
        }
    }
}

extern "C" void kernel_launch(void* const* d_in, const int* in_sizes, int n_in,
                              void* d_out, int out_size) {
    const float* out = (const float*)d_in[0];  // output (32, 425, 64, 64)
    const float* tgt = (const float*)d_in[1];  // target (32, 250)
    (void)in_sizes; (void)n_in; (void)out_size;

    k_targets<<<NBB, 64>>>(out, tgt);
    k_main<<<GRID_MAIN, TPB>>>(out, (float*)d_out);
}

// round 15
// speedup vs baseline: 1.2994x; 1.2994x over previous
#include <cuda_runtime.h>
#include <math.h>

#define NBB   32
#define NAA   5
#define NCC   80
#define NHH   64
#define NWW   64
#define MAXTG 50
#define CHN   (5 + NCC)          // 85
#define PLANE (NHH * NWW)        // 4096
#define GRID_MAIN (NBB * NAA * 4) // 640
#define TPB   512                 // 2 cells per thread; 16 warps
#define NWARP 16
#define L2E   1.44269504088896f
#define LN2   0.69314718055995f

// -------- device scratch --------
__device__ float4   g_A[NBB * MAXTG];   // {gl, gr, gt, gb}
__device__ float4   g_B[NBB * MAXTG];   // {-0.375*gw*gh, cellg(int bits), tiou, cls}
__device__ float4   g_C[NBB * MAXTG];   // {tx, ty, tw, th}
__device__ int2     g_D[NBB * MAXTG];   // {class-ch0 gmem offset or -1, class idx}
__device__ double   g_loss;
__device__ unsigned g_count;

__constant__ float c_anch[10] = {
    42.3f / 32.f, 55.4f / 32.f, 102.2f / 32.f, 128.3f / 32.f, 161.8f / 32.f,
    259.2f / 32.f, 303.1f / 32.f, 154.9f / 32.f, 359.6f / 32.f, 320.2f / 32.f
};

__device__ __forceinline__ float sigf(float v) {
    return 1.0f / (1.0f + exp2f(v * -L2E));
}

// -------- kernel 1: per-target precompute (32 blocks x 64 threads) --------
__global__ void __launch_bounds__(64) k_targets(const float* __restrict__ out,
                                                const float* __restrict__ tgt) {
    __shared__ int      s_cellg[MAXTG];
    __shared__ unsigned zmask[2];

    int b = blockIdx.x;
    int t = threadIdx.x;

    if (b == 0 && t == 0) { g_loss = 0.0; g_count = 0u; }

    float cls = 0.f, fx = 0.f, fy = 0.f, fw = 0.f, fh = 0.f;
    bool nzf = true;
    if (t < MAXTG) {
        const float* p = tgt + (b * MAXTG + t) * 5;
        cls = p[0]; fx = p[1]; fy = p[2]; fw = p[3]; fh = p[4];
        nzf = (fx != 0.0f);
    }

    unsigned zeros = __ballot_sync(0xffffffffu, !nzf);
    if ((t & 31) == 0) zmask[t >> 5] = zeros;
    __syncthreads();
    int fz0 = __ffs((int)zmask[0]);
    int fz1 = __ffs((int)zmask[1]);
    int first_zero = fz0 ? (fz0 - 1) : (fz1 ? 32 + fz1 - 1 : 1000);

    bool valid = (t < MAXTG) && (t < first_zero);
    int cellg = -1;
    int clsoff = -1;
    int idx = b * MAXTG + t;

    if (t < MAXTG) {
        float gx = fx * (float)NWW;
        float gy = fy * (float)NHH;
        float gw = fw * (float)NWW;
        float gh = fh * (float)NHH;

        int best = 0;
        float bestv = -1e30f;
#pragma unroll
        for (int an = 0; an < NAA; an++) {
            float aw = c_anch[2 * an], ah = c_anch[2 * an + 1];
            float inter = fminf(gw, aw) * fminf(gh, ah);
            float uni = gw * gh + aw * ah - inter;
            float v = inter / uni;
            if (v > bestv) { bestv = v; best = an; }
        }

        int gi = min(max((int)gx, 0), NWW - 1);
        int gj = min(max((int)gy, 0), NHH - 1);
        float awb = c_anch[2 * best], ahb = c_anch[2 * best + 1];

        const float* ob = out + (size_t)(b * (NAA * CHN) + best * CHN) * PLANE
                              + gj * NWW + gi;
        float xx = sigf(ob[0]);
        float yy = sigf(ob[PLANE]);
        float ww = ob[2 * PLANE];
        float hh = ob[3 * PLANE];
        float px = xx + (float)gi;
        float py = yy + (float)gj;
        float pw = exp2f(ww * L2E) * awb;
        float ph = exp2f(hh * L2E) * ahb;

        float iw = fminf(gx + 0.5f * gw, px + 0.5f * pw)
                 - fmaxf(gx - 0.5f * gw, px - 0.5f * pw);
        float ih = fminf(gy + 0.5f * gh, py + 0.5f * ph)
                 - fmaxf(gy - 0.5f * gh, py - 0.5f * ph);
        float inter = fmaxf(iw, 0.f) * fmaxf(ih, 0.f);
        float uni = gw * gh + pw * ph - inter;
        float tiou = inter / uni;

        g_C[idx] = make_float4(gx - (float)gi, gy - (float)gj,
                               log2f(gw / awb) * LN2, log2f(gh / ahb) * LN2);

        cellg = valid ? (best * PLANE + gj * NWW + gi) : -1;
        clsoff = ((b * NAA + best) * CHN + 5) * PLANE + gj * NWW + gi;
        if (valid) {
            g_A[idx] = make_float4(gx - 0.5f * gw, gx + 0.5f * gw,
                                   gy - 0.5f * gh, gy + 0.5f * gh);
            g_B[idx] = make_float4(-0.375f * gw * gh, __int_as_float(cellg), tiou, cls);
        } else {
            g_A[idx] = make_float4(1e30f, -1e30f, 1e30f, -1e30f);
            g_B[idx] = make_float4(0.f, __int_as_float(-1), tiou, cls);
        }
        s_cellg[t] = cellg;
    }
    __syncthreads();

    if (t < MAXTG) {
        // winner = last-t-wins per cell (JAX flat scatter semantics)
        bool winner = valid;
        for (int u = t + 1; u < MAXTG; u++)
            winner = winner && (s_cellg[u] != cellg);
        g_D[idx] = make_int2(winner ? clsoff : -1, (int)cls);
    }
}

// -------- kernel 2: per-cell loss + distributed class loss + final write ----
// grid = 640 blocks; block = 512 threads; thread = 2 consecutive cells.
// Per-warp compacted target lists keep the SIL inner loop branch-free.
__global__ void __launch_bounds__(TPB, 2) k_main(const float* __restrict__ out,
                                                 float* __restrict__ outp) {
    __shared__ float2 s_X[MAXTG];       // {gl, gr}
    __shared__ float2 s_Y[MAXTG];       // {gt, gb}
    __shared__ float  s_nga[MAXTG];     // -0.375*gw*gh
    __shared__ float4 s_Ct[MAXTG];      // {tx, ty, tw, th}
    __shared__ float  s_ti[MAXTG];      // tiou
    __shared__ int    s_map[1024];      // winning target per local cell (-1 none)
    __shared__ float4 s_cbox[NWARP * MAXTG];   // compacted boxes per warp
    __shared__ float  s_cnga[NWARP * MAXTG];   // compacted nga per warp

    int blk = blockIdx.x;
    int q = blk & 3;
    int a = (blk >> 2) % NAA;
    int b = blk / (NAA * 4);
    int tid = threadIdx.x;
    int wid = tid >> 5;
    int lane = tid & 31;

    s_map[tid * 2]     = -1;
    s_map[tid * 2 + 1] = -1;

    int blockbase = a * PLANE + q * 1024;

    if (tid < MAXTG) {
        int o = b * MAXTG + tid;
        float4 bx = g_A[o];
        s_X[tid] = make_float2(bx.x, bx.y);
        s_Y[tid] = make_float2(bx.z, bx.w);
        s_Ct[tid] = g_C[o];
        float4 mb = g_B[o];
        s_nga[tid] = mb.x;
        s_ti[tid]  = mb.z;
    }
    __syncthreads();

    // scatter: max-t wins == JAX last-write-wins
    if (tid < MAXTG) {
        int cellg = __float_as_int(g_B[b * MAXTG + tid].y);
        unsigned m = (unsigned)(cellg - blockbase);
        if (m < 1024u) atomicMax(&s_map[m], tid);
    }

    // ---- class-loss job: issue gathers EARLY so DRAM latency overlaps ----
    bool have_cls = false;
    float cv1 = -1e30f, cv2 = -1e30f, cv3 = -1e30f, cpick = 0.f;
    if (wid >= 13) {
        int tt = (a * 4 + q) + 20 * (wid - 13);
        if (tt < MAXTG) {
            int2 d = g_D[b * MAXTG + tt];
            if (d.x >= 0) {
                have_cls = true;
                const float* cp = out + d.x;
                cv1 = cp[lane * PLANE];
                cv2 = cp[(lane + 32) * PLANE];
                if (lane < 16) cv3 = cp[(lane + 64) * PLANE];
                cpick = cp[d.y * PLANE];
            }
        }
    }

    int lin = q * 1024 + tid * 2;
    int j = lin >> 6;
    int i0 = lin & 63;

    const float* base = out + (size_t)(b * (NAA * CHN) + a * CHN) * PLANE + lin;
    float2 v0 = *reinterpret_cast<const float2*>(base);
    float2 v1 = *reinterpret_cast<const float2*>(base + PLANE);
    float2 v2 = *reinterpret_cast<const float2*>(base + 2 * PLANE);
    float2 v3 = *reinterpret_cast<const float2*>(base + 3 * PLANE);

    float o0[2] = {v0.x, v0.y};
    float o1[2] = {v1.x, v1.y};
    float o2[2] = {v2.x, v2.y};
    float o3[2] = {v3.x, v3.y};

    float aw = c_anch[2 * a], ah = c_anch[2 * a + 1];

    float PXL[2], PXR[2], PYT[2], PYB[2], nPA[2], F[2];
#pragma unroll
    for (int k = 0; k < 2; k++) {
        float pw = exp2f(o2[k] * L2E) * aw;
        float ph = exp2f(o3[k] * L2E) * ah;
        float px = sigf(o0[k]) + (float)(i0 + k);
        float py = sigf(o1[k]) + (float)j;
        PXL[k] = px - 0.5f * pw;
        PXR[k] = px + 0.5f * pw;
        PYT[k] = py - 0.5f * ph;
        PYB[k] = py + 0.5f * ph;
        nPA[k] = -0.375f * pw * ph;
        F[k] = -1e30f;
    }

    // warp-wide y-band (each warp = one grid row)
    float wT = fminf(PYT[0], PYT[1]);
    float wB = fmaxf(PYB[0], PYB[1]);
#pragma unroll
    for (int o = 16; o > 0; o >>= 1) {
        wT = fminf(wT, __shfl_xor_sync(0xffffffffu, wT, o));
        wB = fmaxf(wB, __shfl_xor_sync(0xffffffffu, wB, o));
    }

    __syncthreads();

    // ---- per-warp compaction of surviving targets (warp-synchronous) ----
    // Culled t: gt > wB or gb < wT  =>  ih<0 for all lanes => pm<0, irrelevant.
    int cnt = 0;
    {
        float4* cbox = &s_cbox[wid * MAXTG];
        float*  cnga = &s_cnga[wid * MAXTG];
#pragma unroll
        for (int bt = 0; bt < 64; bt += 32) {
            int t = bt + lane;
            bool live = false;
            float2 gy = make_float2(0.f, 0.f);
            if (t < MAXTG) {
                gy = s_Y[t];
                live = !(gy.x > wB || gy.y < wT);
            }
            unsigned msk = __ballot_sync(0xffffffffu, live);
            if (live) {
                int pos = cnt + __popc(msk & ((1u << lane) - 1u));
                float2 gx = s_X[t];
                cbox[pos] = make_float4(gx.x, gx.y, gy.x, gy.y);
                cnga[pos] = s_nga[t];
            }
            cnt += __popc(msk);
        }
    }

    // ---- SIL loop: branch-free over compacted list ----
    {
        const float4* cbox = &s_cbox[wid * MAXTG];
        const float*  cnga = &s_cnga[wid * MAXTG];
#pragma unroll 2
        for (int i = 0; i < cnt; i++) {
            float4 bx = cbox[i];
            float nga = cnga[i];
#pragma unroll
            for (int k = 0; k < 2; k++) {
                float iw  = fminf(PXR[k], bx.y) - fmaxf(PXL[k], bx.x);
                float iwc = fmaxf(iw, 0.f);
                float ih  = fminf(PYB[k], bx.w) - fmaxf(PYT[k], bx.z);
                float pm  = iwc * ih + (nPA[k] + nga);
                F[k] = fmaxf(F[k], pm);
            }
        }
    }

    // ---- per-cell epilogue (float accumulation) ----
    float2 v4 = *reinterpret_cast<const float2*>(base + 4 * PLANE);
    float e4[2] = {v4.x, v4.y};

    float facc = 0.0f;
#pragma unroll
    for (int k = 0; k < 2; k++) {
        float X = sigf(o0[k]);
        float Y = sigf(o1[k]);
        float W = o2[k];
        float H = o3[k];
        float C = sigf(e4[k]);
        int S = s_map[tid * 2 + k];
        if (S < 0) {
            float dx = X - 0.5f;
            float dy = Y - 0.5f;
            float l = dx * dx + dy * dy + W * W + H * H;
            float lc = (F[k] > 0.f) ? 0.f : C * C;
            facc += 0.5f * (l + lc);
        } else {
            float4 tc = s_Ct[S];
            float dx = X - tc.x;
            float dy = Y - tc.y;
            float dw = W - tc.z;
            float dh = H - tc.w;
            float dc = C - s_ti[S];
            float l = dx * dx + dy * dy + dw * dw + dh * dh;
            facc += 0.5f * l + 2.5f * (dc * dc);
        }
    }

    // ---- class-loss epilogue (warps 13..15, data already in flight) ----
    if (have_cls) {
        float m = fmaxf(fmaxf(cv1, cv2), cv3);
#pragma unroll
        for (int o = 16; o > 0; o >>= 1)
            m = fmaxf(m, __shfl_xor_sync(0xffffffffu, m, o));
        float e = exp2f((cv1 - m) * L2E) + exp2f((cv2 - m) * L2E)
                + ((lane < 16) ? exp2f((cv3 - m) * L2E) : 0.f);
#pragma unroll
        for (int o = 16; o > 0; o >>= 1)
            e += __shfl_xor_sync(0xffffffffu, e, o);
        if (lane == 0) {
            float lz = m + log2f(e) * LN2;
            facc += lz - cpick;
        }
    }

    // ---- block reduction: float within warp, double across warps ----
    for (int off = 16; off > 0; off >>= 1)
        facc += __shfl_down_sync(0xffffffffu, facc, off);
    __shared__ double s_red[NWARP];
    if ((tid & 31) == 0) s_red[tid >> 5] = (double)facc;
    __syncthreads();
    if (tid == 0) {
        double s = 0.0;
        for (int wsl = 0; wsl < NWARP; wsl++) s += s_red[wsl];
        atomicAdd(&g_loss, s);
        __threadfence();
        unsigned old = atomicAdd(&g_count, 1u);
        if (old == (unsigned)(GRID_MAIN - 1)) {
            double total = *(volatile double*)&g_loss;
            outp[0] = (float)total;
        }
    }
}

extern "C" void kernel_launch(void* const* d_in, const int* in_sizes, int n_in,
                              void* d_out, int out_size) {
    const float* out = (const float*)d_in[0];  // output (32, 425, 64, 64)
    const float* tgt = (const float*)d_in[1];  // target (32, 250)
    (void)in_sizes; (void)n_in; (void)out_size;

    k_targets<<<NBB, 64>>>(out, tgt);
    k_main<<<GRID_MAIN, TPB>>>(out, (float*)d_out);
}

// round 16
// speedup vs baseline: 1.4189x; 1.0920x over previous
#include <cuda_runtime.h>
#include <math.h>

#define NBB   32
#define NAA   5
#define NCC   80
#define NHH   64
#define NWW   64
#define MAXTG 50
#define CHN   (5 + NCC)          // 85
#define PLANE (NHH * NWW)        // 4096
#define GRID_MAIN (NBB * NAA * 4) // 640
#define TPB   512                 // 2 cells per thread; 16 warps
#define NWARP 16
#define L2E   1.44269504088896f
#define LN2   0.69314718055995f

// -------- device scratch --------
__device__ float4   g_A[NBB * MAXTG];   // {gl, gr, gt, gb}
__device__ float4   g_B[NBB * MAXTG];   // {-0.375*gw*gh, cellg(int bits), tiou, cls}
__device__ float4   g_C[NBB * MAXTG];   // {tx, ty, tw, th}
__device__ int2     g_D[NBB * MAXTG];   // {class-ch0 gmem offset or -1, class idx}
__device__ double   g_loss;
__device__ unsigned g_count;

__constant__ float c_anch[10] = {
    42.3f / 32.f, 55.4f / 32.f, 102.2f / 32.f, 128.3f / 32.f, 161.8f / 32.f,
    259.2f / 32.f, 303.1f / 32.f, 154.9f / 32.f, 359.6f / 32.f, 320.2f / 32.f
};

__device__ __forceinline__ float frcp(float x) {
    float r;
    asm("rcp.approx.f32 %0, %1;" : "=f"(r) : "f"(x));
    return r;
}

// fast sigmoid: MUFU.EX2 + FADD + MUFU.RCP
__device__ __forceinline__ float sigf(float v) {
    return frcp(1.0f + exp2f(v * -L2E));
}

// -------- kernel 1: per-target precompute (32 blocks x 64 threads) --------
__global__ void __launch_bounds__(64) k_targets(const float* __restrict__ out,
                                                const float* __restrict__ tgt) {
    __shared__ int      s_cellg[MAXTG];
    __shared__ unsigned zmask[2];

    int b = blockIdx.x;
    int t = threadIdx.x;

    if (b == 0 && t == 0) { g_loss = 0.0; g_count = 0u; }

    float cls = 0.f, fx = 0.f, fy = 0.f, fw = 0.f, fh = 0.f;
    bool nzf = true;
    if (t < MAXTG) {
        const float* p = tgt + (b * MAXTG + t) * 5;
        cls = p[0]; fx = p[1]; fy = p[2]; fw = p[3]; fh = p[4];
        nzf = (fx != 0.0f);
    }

    unsigned zeros = __ballot_sync(0xffffffffu, !nzf);
    if ((t & 31) == 0) zmask[t >> 5] = zeros;
    __syncthreads();
    int fz0 = __ffs((int)zmask[0]);
    int fz1 = __ffs((int)zmask[1]);
    int first_zero = fz0 ? (fz0 - 1) : (fz1 ? 32 + fz1 - 1 : 1000);

    bool valid = (t < MAXTG) && (t < first_zero);
    int cellg = -1;
    int clsoff = -1;
    int idx = b * MAXTG + t;

    if (t < MAXTG) {
        float gx = fx * (float)NWW;
        float gy = fy * (float)NHH;
        float gw = fw * (float)NWW;
        float gh = fh * (float)NHH;

        int best = 0;
        float bestv = -1e30f;
#pragma unroll
        for (int an = 0; an < NAA; an++) {
            float aw = c_anch[2 * an], ah = c_anch[2 * an + 1];
            float inter = fminf(gw, aw) * fminf(gh, ah);
            float uni = gw * gh + aw * ah - inter;
            float v = inter / uni;
            if (v > bestv) { bestv = v; best = an; }
        }

        int gi = min(max((int)gx, 0), NWW - 1);
        int gj = min(max((int)gy, 0), NHH - 1);
        float awb = c_anch[2 * best], ahb = c_anch[2 * best + 1];

        const float* ob = out + (size_t)(b * (NAA * CHN) + best * CHN) * PLANE
                              + gj * NWW + gi;
        float xx = sigf(ob[0]);
        float yy = sigf(ob[PLANE]);
        float ww = ob[2 * PLANE];
        float hh = ob[3 * PLANE];
        float px = xx + (float)gi;
        float py = yy + (float)gj;
        float pw = exp2f(ww * L2E) * awb;
        float ph = exp2f(hh * L2E) * ahb;

        float iw = fminf(gx + 0.5f * gw, px + 0.5f * pw)
                 - fmaxf(gx - 0.5f * gw, px - 0.5f * pw);
        float ih = fminf(gy + 0.5f * gh, py + 0.5f * ph)
                 - fmaxf(gy - 0.5f * gh, py - 0.5f * ph);
        float inter = fmaxf(iw, 0.f) * fmaxf(ih, 0.f);
        float uni = gw * gh + pw * ph - inter;
        float tiou = inter / uni;

        g_C[idx] = make_float4(gx - (float)gi, gy - (float)gj,
                               log2f(gw / awb) * LN2, log2f(gh / ahb) * LN2);

        cellg = valid ? (best * PLANE + gj * NWW + gi) : -1;
        clsoff = ((b * NAA + best) * CHN + 5) * PLANE + gj * NWW + gi;
        if (valid) {
            g_A[idx] = make_float4(gx - 0.5f * gw, gx + 0.5f * gw,
                                   gy - 0.5f * gh, gy + 0.5f * gh);
            g_B[idx] = make_float4(-0.375f * gw * gh, __int_as_float(cellg), tiou, cls);
        } else {
            g_A[idx] = make_float4(1e30f, -1e30f, 1e30f, -1e30f);
            g_B[idx] = make_float4(0.f, __int_as_float(-1), tiou, cls);
        }
        s_cellg[t] = cellg;
    }
    __syncthreads();

    if (t < MAXTG) {
        // winner = last-t-wins per cell (JAX flat scatter semantics)
        bool winner = valid;
        for (int u = t + 1; u < MAXTG; u++)
            winner = winner && (s_cellg[u] != cellg);
        g_D[idx] = make_int2(winner ? clsoff : -1, (int)cls);
    }
}

// -------- kernel 2: per-cell loss + distributed class loss + final write ----
// grid = 640 blocks; block = 512 threads; thread = 2 consecutive cells.
// Per-warp compacted target lists keep the SIL inner loop branch-free.
__global__ void __launch_bounds__(TPB, 2) k_main(const float* __restrict__ out,
                                                 float* __restrict__ outp) {
    __shared__ float2 s_X[MAXTG];       // {gl, gr}
    __shared__ float2 s_Y[MAXTG];       // {gt, gb}
    __shared__ float  s_nga[MAXTG];     // -0.375*gw*gh
    __shared__ float4 s_Ct[MAXTG];      // {tx, ty, tw, th}
    __shared__ float  s_ti[MAXTG];      // tiou
    __shared__ int    s_map[1024];      // winning target per local cell (-1 none)
    __shared__ float4 s_cbox[NWARP * MAXTG];   // compacted boxes per warp
    __shared__ float  s_cnga[NWARP * MAXTG];   // compacted nga per warp

    int blk = blockIdx.x;
    int q = blk & 3;
    int a = (blk >> 2) % NAA;
    int b = blk / (NAA * 4);
    int tid = threadIdx.x;
    int wid = tid >> 5;
    int lane = tid & 31;

    s_map[tid * 2]     = -1;
    s_map[tid * 2 + 1] = -1;

    int blockbase = a * PLANE + q * 1024;

    if (tid < MAXTG) {
        int o = b * MAXTG + tid;
        float4 bx = g_A[o];
        s_X[tid] = make_float2(bx.x, bx.y);
        s_Y[tid] = make_float2(bx.z, bx.w);
        s_Ct[tid] = g_C[o];
        float4 mb = g_B[o];
        s_nga[tid] = mb.x;
        s_ti[tid]  = mb.z;
    }
    __syncthreads();

    // scatter: max-t wins == JAX last-write-wins
    if (tid < MAXTG) {
        int cellg = __float_as_int(g_B[b * MAXTG + tid].y);
        unsigned m = (unsigned)(cellg - blockbase);
        if (m < 1024u) atomicMax(&s_map[m], tid);
    }

    // ---- class-loss job: issue gathers EARLY so DRAM latency overlaps ----
    bool have_cls = false;
    float cv1 = -1e30f, cv2 = -1e30f, cv3 = -1e30f, cpick = 0.f;
    if (wid >= 13) {
        int tt = (a * 4 + q) + 20 * (wid - 13);
        if (tt < MAXTG) {
            int2 d = g_D[b * MAXTG + tt];
            if (d.x >= 0) {
                have_cls = true;
                const float* cp = out + d.x;
                cv1 = cp[lane * PLANE];
                cv2 = cp[(lane + 32) * PLANE];
                if (lane < 16) cv3 = cp[(lane + 64) * PLANE];
                cpick = cp[d.y * PLANE];
            }
        }
    }

    int lin = q * 1024 + tid * 2;
    int j = lin >> 6;
    int i0 = lin & 63;

    const float* base = out + (size_t)(b * (NAA * CHN) + a * CHN) * PLANE + lin;
    float2 v0 = *reinterpret_cast<const float2*>(base);
    float2 v1 = *reinterpret_cast<const float2*>(base + PLANE);
    float2 v2 = *reinterpret_cast<const float2*>(base + 2 * PLANE);
    float2 v3 = *reinterpret_cast<const float2*>(base + 3 * PLANE);

    float o0[2] = {v0.x, v0.y};
    float o1[2] = {v1.x, v1.y};
    float o2[2] = {v2.x, v2.y};
    float o3[2] = {v3.x, v3.y};

    float aw = c_anch[2 * a], ah = c_anch[2 * a + 1];

    // keep PX/PY so the epilogue recovers sigmoids without recompute
    float PX[2], PY[2], PXL[2], PXR[2], PYT[2], PYB[2], nPA[2], F[2];
#pragma unroll
    for (int k = 0; k < 2; k++) {
        float pw = exp2f(o2[k] * L2E) * aw;
        float ph = exp2f(o3[k] * L2E) * ah;
        PX[k] = sigf(o0[k]) + (float)(i0 + k);
        PY[k] = sigf(o1[k]) + (float)j;
        PXL[k] = PX[k] - 0.5f * pw;
        PXR[k] = PX[k] + 0.5f * pw;
        PYT[k] = PY[k] - 0.5f * ph;
        PYB[k] = PY[k] + 0.5f * ph;
        nPA[k] = -0.375f * pw * ph;
        F[k] = -1e30f;
    }

    // warp-wide y-band (each warp = one grid row)
    float wT = fminf(PYT[0], PYT[1]);
    float wB = fmaxf(PYB[0], PYB[1]);
#pragma unroll
    for (int o = 16; o > 0; o >>= 1) {
        wT = fminf(wT, __shfl_xor_sync(0xffffffffu, wT, o));
        wB = fmaxf(wB, __shfl_xor_sync(0xffffffffu, wB, o));
    }

    __syncthreads();

    // ---- per-warp compaction of surviving targets (warp-synchronous) ----
    // Culled t: gt > wB or gb < wT  =>  ih<0 for all lanes => pm<0, irrelevant.
    int cnt = 0;
    {
        float4* cbox = &s_cbox[wid * MAXTG];
        float*  cnga = &s_cnga[wid * MAXTG];
#pragma unroll
        for (int bt = 0; bt < 64; bt += 32) {
            int t = bt + lane;
            bool live = false;
            float2 gy = make_float2(0.f, 0.f);
            if (t < MAXTG) {
                gy = s_Y[t];
                live = !(gy.x > wB || gy.y < wT);
            }
            unsigned msk = __ballot_sync(0xffffffffu, live);
            if (live) {
                int pos = cnt + __popc(msk & ((1u << lane) - 1u));
                float2 gx = s_X[t];
                cbox[pos] = make_float4(gx.x, gx.y, gy.x, gy.y);
                cnga[pos] = s_nga[t];
            }
            cnt += __popc(msk);
        }
    }

    // ---- SIL loop: branch-free over compacted list ----
    {
        const float4* cbox = &s_cbox[wid * MAXTG];
        const float*  cnga = &s_cnga[wid * MAXTG];
#pragma unroll 2
        for (int i = 0; i < cnt; i++) {
            float4 bx = cbox[i];
            float nga = cnga[i];
#pragma unroll
            for (int k = 0; k < 2; k++) {
                float iw  = fminf(PXR[k], bx.y) - fmaxf(PXL[k], bx.x);
                float iwc = fmaxf(iw, 0.f);
                float ih  = fminf(PYB[k], bx.w) - fmaxf(PYT[k], bx.z);
                float pm  = iwc * ih + (nPA[k] + nga);
                F[k] = fmaxf(F[k], pm);
            }
        }
    }

    // ---- per-cell epilogue (float accumulation) ----
    float2 v4 = *reinterpret_cast<const float2*>(base + 4 * PLANE);
    float e4[2] = {v4.x, v4.y};

    float facc = 0.0f;
#pragma unroll
    for (int k = 0; k < 2; k++) {
        float X = PX[k] - (float)(i0 + k);     // recover prologue sigmoid
        float Y = PY[k] - (float)j;
        float W = o2[k];
        float H = o3[k];
        float C = sigf(e4[k]);
        int S = s_map[tid * 2 + k];
        if (S < 0) {
            float dx = X - 0.5f;
            float dy = Y - 0.5f;
            float l = dx * dx + dy * dy + W * W + H * H;
            float lc = (F[k] > 0.f) ? 0.f : C * C;
            facc += 0.5f * (l + lc);
        } else {
            float4 tc = s_Ct[S];
            float dx = X - tc.x;
            float dy = Y - tc.y;
            float dw = W - tc.z;
            float dh = H - tc.w;
            float dc = C - s_ti[S];
            float l = dx * dx + dy * dy + dw * dw + dh * dh;
            facc += 0.5f * l + 2.5f * (dc * dc);
        }
    }

    // ---- class-loss epilogue (warps 13..15, data already in flight) ----
    if (have_cls) {
        float m = fmaxf(fmaxf(cv1, cv2), cv3);
#pragma unroll
        for (int o = 16; o > 0; o >>= 1)
            m = fmaxf(m, __shfl_xor_sync(0xffffffffu, m, o));
        float e = exp2f((cv1 - m) * L2E) + exp2f((cv2 - m) * L2E)
                + ((lane < 16) ? exp2f((cv3 - m) * L2E) : 0.f);
#pragma unroll
        for (int o = 16; o > 0; o >>= 1)
            e += __shfl_xor_sync(0xffffffffu, e, o);
        if (lane == 0) {
            float lz = m + log2f(e) * LN2;
            facc += lz - cpick;
        }
    }

    // ---- block reduction: float within warp, double across warps ----
    for (int off = 16; off > 0; off >>= 1)
        facc += __shfl_down_sync(0xffffffffu, facc, off);
    __shared__ double s_red[NWARP];
    if ((tid & 31) == 0) s_red[tid >> 5] = (double)facc;
    __syncthreads();
    if (tid == 0) {
        double s = 0.0;
        for (int wsl = 0; wsl < NWARP; wsl++) s += s_red[wsl];
        atomicAdd(&g_loss, s);
        __threadfence();
        unsigned old = atomicAdd(&g_count, 1u);
        if (old == (unsigned)(GRID_MAIN - 1)) {
            double total = *(volatile double*)&g_loss;
            outp[0] = (float)total;
        }
    }
}

extern "C" void kernel_launch(void* const* d_in, const int* in_sizes, int n_in,
                              void* d_out, int out_size) {
    const float* out = (const float*)d_in[0];  // output (32, 425, 64, 64)
    const float* tgt = (const float*)d_in[1];  // target (32, 250)
    (void)in_sizes; (void)n_in; (void)out_size;

    k_targets<<<NBB, 64>>>(out, tgt);
    k_main<<<GRID_MAIN, TPB>>>(out, (float*)d_out);
}